// round 12
// baseline (speedup 1.0000x reference)
#include <cuda_runtime.h>
#include <cuda_bf16.h>
#include <cstdint>

#define BLK   512
#define SUB   512              // edges per subtile (== BLK)
#define NSUB  4
#define SUPER (SUB * NSUB)     // 2048 edges per supertile
#define NB    10

#define N_POS_MAX  100000
#define N_QPOS_MAX 10000

// FC = 1.14136 * e^2 * sqrt(10)
#define FC_CONST 26.6692997f
#define SQRT3_F  1.7320508075688772f

// Padded pos table (16B rows -> single LDG.128 per gather).
__device__ float4 g_pos4[N_POS_MAX];

__global__ void pad_pos_kernel(const float* __restrict__ pos, int n_pos)
{
    int i = blockIdx.x * blockDim.x + threadIdx.x;
    if (i < n_pos)
        g_pos4[i] = make_float4(pos[3*i], pos[3*i+1], pos[3*i+2], 0.f);
}

__device__ __forceinline__ uint32_t smem_u32(const void* p) {
    uint32_t a;
    asm("{ .reg .u64 t; cvta.to.shared.u64 t, %1; cvt.u32.u64 %0, t; }"
        : "=r"(a) : "l"(p));
    return a;
}

// Dynamic SMEM layout:
//   [0)                 s_sh  : 2 * SUB*9  floats  (double-buffered SH tile)
//   [+2*SUB*9*4)        s_emb : 2 * SUB*10 floats  (double-buffered embed tile)
//   [+2*SUB*10*4)       s_qx/s_qy/s_qz : 3 * N_QPOS_MAX floats (qpos SoA table)
#define SMEM_SH_BYTES   (2 * SUB * 9  * 4)
#define SMEM_EMB_BYTES  (2 * SUB * NB * 4)
#define SMEM_Q_BYTES    (3 * N_QPOS_MAX * 4)
#define SMEM_TOTAL      (SMEM_SH_BYTES + SMEM_EMB_BYTES + SMEM_Q_BYTES)

__global__ void __launch_bounds__(BLK, 1) qsh_kernel(
    const int*   __restrict__ esrc,    // [E] -> qpos rows
    const int*   __restrict__ edst,    // [E] -> pos rows
    const float* __restrict__ qpos,    // [n_qpos*3] raw (copied to SMEM)
    float*       __restrict__ out,     // [E*9] sh | [E*10] embed
    int E, int n_qpos, long long nSuper)
{
    extern __shared__ __align__(16) char smem[];
    float* s_sh  = (float*)smem;
    float* s_emb = (float*)(smem + SMEM_SH_BYTES);
    float* s_qx  = (float*)(smem + SMEM_SH_BYTES + SMEM_EMB_BYTES);
    float* s_qy  = s_qx + N_QPOS_MAX;
    float* s_qz  = s_qy + N_QPOS_MAX;

    const int t = threadIdx.x;

    // ---- one-time: qpos table -> SMEM (SoA) ----
    for (int i = t; i < n_qpos * 3; i += BLK) {
        float v = qpos[i];
        int r = i / 3, c = i - 3 * r;
        float* dst = (c == 0) ? s_qx : (c == 1) ? s_qy : s_qz;
        dst[r] = v;
    }
    __syncthreads();

    float* out_sh  = out;
    float* out_emb = out + (long long)E * 9;
    const bool aligned4 = ((E & 3) == 0);

    for (long long sup = blockIdx.x; sup < nSuper; sup += gridDim.x) {
        const long long base = sup * (long long)SUPER;

        // ---- prefetch: indices + pos gathers for all 4 subtiles ----
        int   si[NSUB], di[NSUB];
        float4 b[NSUB];
        #pragma unroll
        for (int s = 0; s < NSUB; s++) {
            long long e = base + (long long)s * SUB + t;
            bool v = e < (long long)E;
            si[s] = v ? esrc[e] : 0;
            di[s] = v ? edst[e] : 0;
        }
        #pragma unroll
        for (int s = 0; s < NSUB; s++)
            b[s] = __ldg(&g_pos4[di[s]]);          // 4 LDG.128 in flight

        #pragma unroll
        for (int s = 0; s < NSUB; s++) {
            const long long ebase = base + (long long)s * SUB;
            const int nval = (int)min((long long)SUB, (long long)E - ebase);
            if (nval > 0) {
                const int p = s & 1;               // ping-pong buffer
                float* tsh  = s_sh  + p * SUB * 9;
                float* temb = s_emb + p * SUB * NB;

                // ---- compute (overlaps in-flight TMA of buffer p) ----
                const float ax = s_qx[si[s]];
                const float ay = s_qy[si[s]];
                const float az = s_qz[si[s]];
                const float vx = ax - b[s].x;
                const float vy = ay - b[s].y;
                const float vz = az - b[s].z;

                const float s2   = vx*vx + vy*vy + vz*vz;
                const float rinv = (s2 > 0.f) ? rsqrtf(s2) : 0.f;
                const float r    = s2 * rinv;
                const float x = vx * rinv, y = vy * rinv, z = vz * rinv;

                const float sh4 = SQRT3_F * x * z;
                const float sh5 = SQRT3_F * x * y;
                const float sh6 = y*y - 0.5f * (x*x + z*z);
                const float sh7 = SQRT3_F * y * z;
                const float sh8 = 0.5f * SQRT3_F * (z*z - x*x);

                // embed: d_j = 11r-(j+1); nonzero iff |d_j|<1; at most 2 of 10.
                // sus(1+d)*sus(1-d) = exp(-2/(1-d^2))
                const float tt = r * 11.0f;
                const int   k  = (int)tt;
                const float d1 = tt - (float)k;
                const float d2 = d1 - 1.f;
                float v1 = 0.f, v2 = 0.f;
                if (k >= 1 && k <= NB) v1 = FC_CONST * __expf(-2.f / (1.f - d1*d1));
                if (k < NB && d2 > -1.f) v2 = FC_CONST * __expf(-2.f / (1.f - d2*d2));
                const int k1 = k - 1, k2 = k;

                // ---- buffer p free? (group from subtile s-2 must be done) ----
                if (t == 0)
                    asm volatile("cp.async.bulk.wait_group 1;" ::: "memory");
                __syncthreads();

                // ---- stage own slots (stride 9 conflict-free; stride 10 ~2-way) ----
                float* msh = tsh + t * 9;
                msh[0] = 1.f;  msh[1] = x;  msh[2] = y;  msh[3] = z;
                msh[4] = sh4;  msh[5] = sh5; msh[6] = sh6;
                msh[7] = sh7;  msh[8] = sh8;

                float* memb = temb + t * NB;
                #pragma unroll
                for (int j = 0; j < NB; j++)
                    memb[j] = (j == k1) ? v1 : ((j == k2) ? v2 : 0.f);

                __syncthreads();

                // ---- drain buffer p ----
                if (nval == SUB && aligned4) {
                    if (t == 0) {
                        asm volatile("fence.proxy.async.shared::cta;" ::: "memory");
                        void* gsh = (void*)(out_sh  + ebase * 9);
                        void* gem = (void*)(out_emb + ebase * NB);
                        uint32_t ssh = smem_u32(tsh);
                        uint32_t sem = smem_u32(temb);
                        asm volatile(
                            "cp.async.bulk.global.shared::cta.bulk_group [%0], [%1], %2;"
                            :: "l"(gsh), "r"(ssh), "r"((uint32_t)(SUB * 9 * 4)) : "memory");
                        asm volatile(
                            "cp.async.bulk.global.shared::cta.bulk_group [%0], [%1], %2;"
                            :: "l"(gem), "r"(sem), "r"((uint32_t)(SUB * NB * 4)) : "memory");
                        asm volatile("cp.async.bulk.commit_group;" ::: "memory");
                    }
                } else {
                    for (int i = t; i < nval * 9;  i += BLK)
                        out_sh [ebase * 9  + i] = tsh [i];
                    for (int i = t; i < nval * NB; i += BLK)
                        out_emb[ebase * NB + i] = temb[i];
                    __syncthreads();   // reads done before buffer reuse
                }
            }
        }
    }

    // drain all outstanding TMA groups before exit
    if (t == 0)
        asm volatile("cp.async.bulk.wait_group 0;" ::: "memory");
}

extern "C" void kernel_launch(void* const* d_in, const int* in_sizes, int n_in,
                              void* d_out, int out_size)
{
    const float* pos  = (const float*)d_in[0];
    const float* qpos = (const float*)d_in[1];
    const int*   esrc = (const int*)  d_in[2];
    const int*   edst = (const int*)  d_in[3];

    const int n_pos  = in_sizes[0] / 3;
    const int n_qpos = in_sizes[1] / 3;
    const int E      = in_sizes[2];

    pad_pos_kernel<<<(n_pos + 255) / 256, 256>>>(pos, n_pos);

    static int sm_count = 0;   // device attribute: constant for the run
    if (sm_count == 0) {
        int dev = 0;
        cudaGetDevice(&dev);
        cudaDeviceGetAttribute(&sm_count, cudaDevAttrMultiProcessorCount, dev);
        cudaFuncSetAttribute(qsh_kernel,
                             cudaFuncAttributeMaxDynamicSharedMemorySize,
                             SMEM_TOTAL);
    }

    const long long nSuper = ((long long)E + SUPER - 1) / SUPER;
    int grid = (int)((nSuper < (long long)sm_count) ? nSuper : (long long)sm_count);

    qsh_kernel<<<grid, BLK, SMEM_TOTAL>>>(esrc, edst, qpos, (float*)d_out,
                                          E, n_qpos, nSuper);
}

// round 14
// speedup vs baseline: 1.0228x; 1.0228x over previous
#include <cuda_runtime.h>
#include <cuda_bf16.h>
#include <cstdint>

#define BLK   1024
#define SUB   1024             // edges per subtile (== BLK)
#define NSUB  2
#define SUPER (SUB * NSUB)     // 2048 edges per supertile
#define NB    10

#define N_POS_MAX  100000
#define N_QPOS_MAX 10000

// FC = 1.14136 * e^2 * sqrt(10)
#define FC_CONST 26.6692997f
#define SQRT3_F  1.7320508075688772f

// Padded pos table (16B rows -> single LDG.128 per gather).
__device__ float4 g_pos4[N_POS_MAX];

__global__ void pad_pos_kernel(const float* __restrict__ pos, int n_pos)
{
    int i = blockIdx.x * blockDim.x + threadIdx.x;
    if (i < n_pos)
        g_pos4[i] = make_float4(pos[3*i], pos[3*i+1], pos[3*i+2], 0.f);
}

__device__ __forceinline__ uint32_t smem_u32(const void* p) {
    uint32_t a;
    asm("{ .reg .u64 t; cvta.to.shared.u64 t, %1; cvt.u32.u64 %0, t; }"
        : "=r"(a) : "l"(p));
    return a;
}

// Dynamic SMEM layout:
//   [0)              s_sh  : SUB*9  floats  (staging, single buffer)
//   [+SUB*9*4)       s_emb : SUB*10 floats
//   [+SUB*10*4)      s_qx/s_qy/s_qz : 3 * N_QPOS_MAX floats (qpos SoA table)
#define SMEM_SH_BYTES   (SUB * 9  * 4)
#define SMEM_EMB_BYTES  (SUB * NB * 4)
#define SMEM_Q_BYTES    (3 * N_QPOS_MAX * 4)
#define SMEM_TOTAL      (SMEM_SH_BYTES + SMEM_EMB_BYTES + SMEM_Q_BYTES)

__global__ void __launch_bounds__(BLK, 1) qsh_kernel(
    const int*   __restrict__ esrc,    // [E] -> qpos rows
    const int*   __restrict__ edst,    // [E] -> pos rows
    const float* __restrict__ qpos,    // [n_qpos*3] raw (copied to SMEM)
    float*       __restrict__ out,     // [E*9] sh | [E*10] embed
    int E, int n_qpos, long long nSuper)
{
    extern __shared__ __align__(16) char smem[];
    float* s_sh  = (float*)smem;
    float* s_emb = (float*)(smem + SMEM_SH_BYTES);
    float* s_qx  = (float*)(smem + SMEM_SH_BYTES + SMEM_EMB_BYTES);
    float* s_qy  = s_qx + N_QPOS_MAX;
    float* s_qz  = s_qy + N_QPOS_MAX;

    const int t = threadIdx.x;

    // ---- one-time: qpos table -> SMEM (SoA) ----
    for (int i = t; i < n_qpos * 3; i += BLK) {
        float v = qpos[i];
        int r = i / 3, c = i - 3 * r;
        float* dst = (c == 0) ? s_qx : (c == 1) ? s_qy : s_qz;
        dst[r] = v;
    }
    __syncthreads();

    float* out_sh  = out;
    float* out_emb = out + (long long)E * 9;
    const bool aligned4 = ((E & 3) == 0);

    for (long long sup = blockIdx.x; sup < nSuper; sup += gridDim.x) {
        const long long base = sup * (long long)SUPER;

        // ---- prefetch: indices + pos gathers for both subtiles ----
        int    si[NSUB], di[NSUB];
        float4 b[NSUB];
        #pragma unroll
        for (int s = 0; s < NSUB; s++) {
            long long e = base + (long long)s * SUB + t;
            bool v = e < (long long)E;
            si[s] = v ? esrc[e] : 0;
            di[s] = v ? edst[e] : 0;
        }
        #pragma unroll
        for (int s = 0; s < NSUB; s++)
            b[s] = __ldg(&g_pos4[di[s]]);          // MLP=2 per thread

        #pragma unroll
        for (int s = 0; s < NSUB; s++) {
            const long long ebase = base + (long long)s * SUB;
            const int nval = (int)min((long long)SUB, (long long)E - ebase);
            if (nval > 0) {
                // ---- compute (overlaps in-flight TMA drain of prev tile) ----
                const float ax = s_qx[si[s]];
                const float ay = s_qy[si[s]];
                const float az = s_qz[si[s]];
                const float vx = ax - b[s].x;
                const float vy = ay - b[s].y;
                const float vz = az - b[s].z;

                const float s2   = vx*vx + vy*vy + vz*vz;
                const float rinv = (s2 > 0.f) ? rsqrtf(s2) : 0.f;
                const float r    = s2 * rinv;
                const float x = vx * rinv, y = vy * rinv, z = vz * rinv;

                const float sh4 = SQRT3_F * x * z;
                const float sh5 = SQRT3_F * x * y;
                const float sh6 = y*y - 0.5f * (x*x + z*z);
                const float sh7 = SQRT3_F * y * z;
                const float sh8 = 0.5f * SQRT3_F * (z*z - x*x);

                // embed: d_j = 11r-(j+1); nonzero iff |d_j|<1; at most 2 of 10.
                // sus(1+d)*sus(1-d) = exp(-2/(1-d^2))
                const float tt = r * 11.0f;
                const int   k  = (int)tt;
                const float d1 = tt - (float)k;
                const float d2 = d1 - 1.f;
                float v1 = 0.f, v2 = 0.f;
                if (k >= 1 && k <= NB) v1 = FC_CONST * __expf(-2.f / (1.f - d1*d1));
                if (k < NB && d2 > -1.f) v2 = FC_CONST * __expf(-2.f / (1.f - d2*d2));
                const int k1 = k - 1, k2 = k;

                // ---- staging buffer free? (previous tile's TMA must be done) ----
                if (t == 0)
                    asm volatile("cp.async.bulk.wait_group 0;" ::: "memory");
                __syncthreads();

                // ---- stage own slots (stride 9 conflict-free; stride 10 ~2-way) ----
                float* msh = s_sh + t * 9;
                msh[0] = 1.f;  msh[1] = x;  msh[2] = y;  msh[3] = z;
                msh[4] = sh4;  msh[5] = sh5; msh[6] = sh6;
                msh[7] = sh7;  msh[8] = sh8;

                float* memb = s_emb + t * NB;
                #pragma unroll
                for (int j = 0; j < NB; j++)
                    memb[j] = (j == k1) ? v1 : ((j == k2) ? v2 : 0.f);

                __syncthreads();

                // ---- drain (async TMA; overlaps next tile's compute) ----
                if (nval == SUB && aligned4) {
                    if (t == 0) {
                        asm volatile("fence.proxy.async.shared::cta;" ::: "memory");
                        void* gsh = (void*)(out_sh  + ebase * 9);
                        void* gem = (void*)(out_emb + ebase * NB);
                        uint32_t ssh = smem_u32(s_sh);
                        uint32_t sem = smem_u32(s_emb);
                        asm volatile(
                            "cp.async.bulk.global.shared::cta.bulk_group [%0], [%1], %2;"
                            :: "l"(gsh), "r"(ssh), "r"((uint32_t)(SUB * 9 * 4)) : "memory");
                        asm volatile(
                            "cp.async.bulk.global.shared::cta.bulk_group [%0], [%1], %2;"
                            :: "l"(gem), "r"(sem), "r"((uint32_t)(SUB * NB * 4)) : "memory");
                        asm volatile("cp.async.bulk.commit_group;" ::: "memory");
                    }
                } else {
                    for (int i = t; i < nval * 9;  i += BLK)
                        out_sh [ebase * 9  + i] = s_sh [i];
                    for (int i = t; i < nval * NB; i += BLK)
                        out_emb[ebase * NB + i] = s_emb[i];
                    __syncthreads();   // reads done before buffer reuse
                }
            }
        }
    }

    // drain all outstanding TMA groups before exit
    if (t == 0)
        asm volatile("cp.async.bulk.wait_group 0;" ::: "memory");
}

extern "C" void kernel_launch(void* const* d_in, const int* in_sizes, int n_in,
                              void* d_out, int out_size)
{
    const float* pos  = (const float*)d_in[0];
    const float* qpos = (const float*)d_in[1];
    const int*   esrc = (const int*)  d_in[2];
    const int*   edst = (const int*)  d_in[3];

    const int n_pos  = in_sizes[0] / 3;
    const int n_qpos = in_sizes[1] / 3;
    const int E      = in_sizes[2];

    pad_pos_kernel<<<(n_pos + 255) / 256, 256>>>(pos, n_pos);

    static int sm_count = 0;   // device attribute: constant for the run
    if (sm_count == 0) {
        int dev = 0;
        cudaGetDevice(&dev);
        cudaDeviceGetAttribute(&sm_count, cudaDevAttrMultiProcessorCount, dev);
        cudaFuncSetAttribute(qsh_kernel,
                             cudaFuncAttributeMaxDynamicSharedMemorySize,
                             SMEM_TOTAL);
    }

    const long long nSuper = ((long long)E + SUPER - 1) / SUPER;
    int grid = (int)((nSuper < (long long)sm_count) ? nSuper : (long long)sm_count);

    qsh_kernel<<<grid, BLK, SMEM_TOTAL>>>(esrc, edst, qpos, (float*)d_out,
                                          E, n_qpos, nSuper);
}